// round 1
// baseline (speedup 1.0000x reference)
#include <cuda_runtime.h>
#include <cstdint>
#include <math.h>

// ---------------- problem constants ----------------
#define BATCH 16384
#define ZD 32
#define NE 512
#define GAMMA 0.99f
#define ONE_M_GAMMA 0.01f
#define BETA 1.0f

#define OFF_SCAL (BATCH * 784)   // 12,845,056: x_rec size
// d_out layout: [x_rec (B*784)][quant][commit][perplexity][emb_new (512*32)]

// ---------------- scratch (no allocation allowed) ----------------
__device__ float g_h1[BATCH * 16 * 14 * 14];   // conv1 out / convt1 out (51.4M)
__device__ float g_h2[BATCH * 32 * 7 * 7];     // conv2/res1 out, fc4/res2 out (25.7M)
__device__ float g_a [BATCH * 224];            // fc1 out / fc3 out
__device__ float g_z [BATCH * ZD];             // fc2 out
__device__ int   g_idx[BATCH];
__device__ float g_enorm[NE];
__device__ float g_counts[NE];
__device__ float g_sums[NE * ZD];
__device__ float g_loss[1];

// ======================================================================
// conv1: x[B,1,28,28] -> relu -> h1[B,16,14,14]   (k4 s2 p1)
// one block per image, 256 threads, naive per-output (cheap layer)
// ======================================================================
__global__ void conv1_kernel(const float* __restrict__ x,
                             const float* __restrict__ w,
                             const float* __restrict__ bias,
                             float* __restrict__ out) {
    __shared__ float img[784];
    __shared__ float ws[256];
    int b = blockIdx.x, t = threadIdx.x;
    const float* ip = x + (size_t)b * 784;
    for (int i = t; i < 784; i += 256) img[i] = ip[i];
    if (t < 256) ws[t] = w[t];
    __syncthreads();
    float* op = out + (size_t)b * 3136;
    for (int o = t; o < 3136; o += 256) {
        int oc = o / 196, s = o % 196, oy = s / 14, ox = s % 14;
        float acc = bias[oc];
        const float* wp = ws + oc * 16;
        #pragma unroll
        for (int ky = 0; ky < 4; ky++) {
            int iy = 2 * oy - 1 + ky;
            if ((unsigned)iy < 28u) {
                #pragma unroll
                for (int kx = 0; kx < 4; kx++) {
                    int ix = 2 * ox - 1 + kx;
                    if ((unsigned)ix < 28u)
                        acc += img[iy * 28 + ix] * wp[ky * 4 + kx];
                }
            }
        }
        op[o] = fmaxf(acc, 0.f);
    }
}

// ======================================================================
// conv2: h1[B,16,14,14] -> h2[B,32,7,7]   (k4 s2 p1, no relu)
// one block per image, 224 threads = (oc=32) x (oy=7); each thread owns
// one output row (7 outputs) -> ~0.75 loads per FMA
// ======================================================================
__global__ void conv2_kernel(const float* __restrict__ in,
                             const float* __restrict__ w,
                             const float* __restrict__ bias,
                             float* __restrict__ out) {
    __shared__ float img[16 * 196];
    int b = blockIdx.x, t = threadIdx.x;   // 224 threads
    const float* ip = in + (size_t)b * 3136;
    for (int i = t; i < 3136; i += 224) img[i] = ip[i];
    __syncthreads();
    int oc = t / 7, oy = t % 7;
    float acc[7];
    float bv = bias[oc];
    #pragma unroll
    for (int j = 0; j < 7; j++) acc[j] = bv;
    for (int ic = 0; ic < 16; ic++) {
        const float* xc = img + ic * 196;
        const float* wp = w + oc * 256 + ic * 16;
        #pragma unroll
        for (int ky = 0; ky < 4; ky++) {
            int iy = 2 * oy - 1 + ky;
            if (iy < 0 || iy >= 14) continue;
            float row[14];
            #pragma unroll
            for (int j = 0; j < 14; j++) row[j] = xc[iy * 14 + j];
            #pragma unroll
            for (int kx = 0; kx < 4; kx++) {
                float wv = __ldg(wp + ky * 4 + kx);
                #pragma unroll
                for (int ox = 0; ox < 7; ox++) {
                    int ix = 2 * ox - 1 + kx;      // compile-time per (ox,kx)
                    if (ix >= 0 && ix < 14) acc[ox] += row[ix] * wv;
                }
            }
        }
    }
    float* op = out + (size_t)b * 1568 + oc * 49 + oy * 7;
    #pragma unroll
    for (int ox = 0; ox < 7; ox++) op[ox] = acc[ox];
}

// ======================================================================
// res stack (in-place): y = relu(x + conv1x1(relu(conv3x3(relu(x)))))
// buf[B,32,7,7]; w1[64,32,3,3]; w2[32,64,1,1]
// block = one image, 448 threads. phase1: (oc=64)x(oy=7) reg-tiled rows.
// ======================================================================
__global__ void res_kernel(float* __restrict__ buf,
                           const float* __restrict__ w1,
                           const float* __restrict__ w2) {
    __shared__ float xin[1568];
    __shared__ float r[64 * 49];
    __shared__ float w2s[2048];
    int b = blockIdx.x, t = threadIdx.x;   // 448 threads
    float* bp = buf + (size_t)b * 1568;
    for (int i = t; i < 1568; i += 448) xin[i] = bp[i];
    for (int i = t; i < 2048; i += 448) w2s[i] = w2[i];
    __syncthreads();

    // phase 1: conv3x3 (32->64) on relu(x), relu output
    {
        int oc = t / 7, oy = t % 7;  // oc 0..63
        float acc[7] = {0.f, 0.f, 0.f, 0.f, 0.f, 0.f, 0.f};
        for (int ic = 0; ic < 32; ic++) {
            const float* xc = xin + ic * 49;
            float row[3][9];
            #pragma unroll
            for (int ky = 0; ky < 3; ky++) {
                int iy = oy - 1 + ky;
                #pragma unroll
                for (int j = 0; j < 9; j++) {
                    int ix = j - 1;
                    row[ky][j] = ((unsigned)iy < 7u && (unsigned)ix < 7u)
                                 ? fmaxf(xc[iy * 7 + ix], 0.f) : 0.f;
                }
            }
            const float* wp = w1 + oc * 288 + ic * 9;
            #pragma unroll
            for (int ky = 0; ky < 3; ky++)
                #pragma unroll
                for (int kx = 0; kx < 3; kx++) {
                    float wv = __ldg(wp + ky * 3 + kx);
                    #pragma unroll
                    for (int ox = 0; ox < 7; ox++)
                        acc[ox] += row[ky][ox + kx] * wv;
                }
        }
        int base = oc * 49 + oy * 7;
        #pragma unroll
        for (int ox = 0; ox < 7; ox++) r[base + ox] = fmaxf(acc[ox], 0.f);
    }
    __syncthreads();

    // phase 2: conv1x1 (64->32) + residual add + relu (first 224 threads)
    if (t < 224) {
        int oc = t / 7, sg = t % 7;
        float acc[7] = {0.f, 0.f, 0.f, 0.f, 0.f, 0.f, 0.f};
        const float* w2p = w2s + oc * 64;
        for (int ic = 0; ic < 64; ic++) {
            float wv = w2p[ic];
            const float* rp = r + ic * 49 + sg * 7;
            #pragma unroll
            for (int j = 0; j < 7; j++) acc[j] += rp[j] * wv;
        }
        int base = oc * 49 + sg * 7;
        #pragma unroll
        for (int j = 0; j < 7; j++)
            bp[base + j] = fmaxf(xin[base + j] + acc[j], 0.f);
    }
}

// ======================================================================
// tiled GEMM: C[M,N] = A[M,K] @ W[N,K]^T + bias, optional relu
// BM=64 BN=64 BK=16, 256 threads, 4x4 micro-tile. M%64==0, K%16==0.
// ======================================================================
template<int RELU>
__global__ void gemm_nt(const float* __restrict__ A,
                        const float* __restrict__ W,
                        const float* __restrict__ bias,
                        float* __restrict__ C,
                        int M, int N, int K) {
    __shared__ float As[16][68];
    __shared__ float Ws[16][68];
    int t = threadIdx.x;
    int tx = t % 16, ty = t / 16;
    int m0 = blockIdx.x * 64, n0 = blockIdx.y * 64;
    int lr = t / 4;            // 0..63
    int lc = (t % 4) * 4;      // 0,4,8,12
    float c[4][4] = {};
    for (int k0 = 0; k0 < K; k0 += 16) {
        float4 av = *(const float4*)(A + (size_t)(m0 + lr) * K + k0 + lc);
        As[lc + 0][lr] = av.x; As[lc + 1][lr] = av.y;
        As[lc + 2][lr] = av.z; As[lc + 3][lr] = av.w;
        int wn = n0 + lr;
        float4 wv = make_float4(0.f, 0.f, 0.f, 0.f);
        if (wn < N) wv = *(const float4*)(W + (size_t)wn * K + k0 + lc);
        Ws[lc + 0][lr] = wv.x; Ws[lc + 1][lr] = wv.y;
        Ws[lc + 2][lr] = wv.z; Ws[lc + 3][lr] = wv.w;
        __syncthreads();
        #pragma unroll
        for (int kk = 0; kk < 16; kk++) {
            float a[4], wq[4];
            #pragma unroll
            for (int i = 0; i < 4; i++) a[i] = As[kk][ty * 4 + i];
            #pragma unroll
            for (int j = 0; j < 4; j++) wq[j] = Ws[kk][tx * 4 + j];
            #pragma unroll
            for (int i = 0; i < 4; i++)
                #pragma unroll
                for (int j = 0; j < 4; j++) c[i][j] += a[i] * wq[j];
        }
        __syncthreads();
    }
    #pragma unroll
    for (int i = 0; i < 4; i++) {
        int m = m0 + ty * 4 + i;
        #pragma unroll
        for (int j = 0; j < 4; j++) {
            int n = n0 + tx * 4 + j;
            if (n < N) {
                float v = c[i][j] + bias[n];
                if (RELU) v = fmaxf(v, 0.f);
                C[(size_t)m * N + n] = v;
            }
        }
    }
}

// ======================================================================
// fc2: z[B,32] = A[B,224] @ w[32,224]^T + b   (no relu)
// ======================================================================
__global__ void fc2_kernel(const float* __restrict__ A,
                           const float* __restrict__ w,
                           const float* __restrict__ bias,
                           float* __restrict__ out) {
    __shared__ float ws[32 * 224];
    int t = threadIdx.x;   // 256
    for (int i = t; i < 7168; i += 256) ws[i] = w[i];
    __syncthreads();
    int n = t & 31, r = t >> 5;
    int b = blockIdx.x * 8 + r;
    const float* ap = A + (size_t)b * 224;
    const float* wp = ws + n * 224;
    float acc = bias[n];
    #pragma unroll 8
    for (int k = 0; k < 224; k++) acc += ap[k] * wp[k];
    out[(size_t)b * 32 + n] = acc;
}

// ======================================================================
// VQ helpers
// ======================================================================
__global__ void enorm_kernel(const float* __restrict__ emb, float* __restrict__ enorm) {
    int e = blockIdx.x * blockDim.x + threadIdx.x;
    if (e < NE) {
        float s = 0.f;
        #pragma unroll
        for (int d = 0; d < ZD; d++) { float v = emb[e * ZD + d]; s += v * v; }
        enorm[e] = s;
    }
}

__global__ void zero_kernel(float* __restrict__ counts, float* __restrict__ sums,
                            float* __restrict__ loss) {
    int i = blockIdx.x * blockDim.x + threadIdx.x;
    if (i < NE) counts[i] = 0.f;
    if (i < NE * ZD) sums[i] = 0.f;
    if (i == 0) loss[0] = 0.f;
}

// one warp per row: argmin over 512 codes (first-min tie-break), then
// counts/sums/loss accumulation via atomics
__global__ void vq_kernel(const float* __restrict__ z,
                          const float* __restrict__ emb,
                          const float* __restrict__ enorm,
                          int* __restrict__ idx,
                          float* __restrict__ counts,
                          float* __restrict__ sums,
                          float* __restrict__ loss) {
    int gw = (blockIdx.x * blockDim.x + threadIdx.x) >> 5;  // row
    int lane = threadIdx.x & 31;
    int wl = threadIdx.x >> 5;
    __shared__ float zs[8][ZD];
    if (gw >= BATCH) return;
    zs[wl][lane] = z[(size_t)gw * ZD + lane];
    __syncwarp();
    float best = 3.4e38f; int bi = NE;
    for (int e = lane; e < NE; e += 32) {
        const float* ep = emb + e * ZD;
        float dot = 0.f;
        #pragma unroll
        for (int d = 0; d < ZD; d++) dot += zs[wl][d] * __ldg(ep + d);
        float s = enorm[e] - 2.f * dot;
        if (s < best) { best = s; bi = e; }
    }
    #pragma unroll
    for (int off = 16; off; off >>= 1) {
        float ob = __shfl_xor_sync(0xffffffffu, best, off);
        int   oi = __shfl_xor_sync(0xffffffffu, bi, off);
        if (ob < best || (ob == best && oi < bi)) { best = ob; bi = oi; }
    }
    float zl = zs[wl][lane];
    float diff = __ldg(emb + (size_t)bi * ZD + lane) - zl;
    float d2 = diff * diff;
    #pragma unroll
    for (int off = 16; off; off >>= 1) d2 += __shfl_xor_sync(0xffffffffu, d2, off);
    if (lane == 0) {
        idx[gw] = bi;
        atomicAdd(&counts[bi], 1.f);
        atomicAdd(loss, d2);
    }
    atomicAdd(&sums[bi * ZD + lane], zl);
}

__global__ void embnew_kernel(const float* __restrict__ m_mat,
                              const float* __restrict__ n_mat,
                              const float* __restrict__ sums,
                              const float* __restrict__ counts,
                              float* __restrict__ out) {
    int i = blockIdx.x * blockDim.x + threadIdx.x;
    if (i < NE * ZD) {
        int e = i >> 5;
        float m = m_mat[i] * GAMMA + sums[i] * ONE_M_GAMMA;
        float n = n_mat[e] * GAMMA + counts[e] * ONE_M_GAMMA;
        out[i] = m / n;
    }
}

__global__ void finalize_kernel(const float* __restrict__ counts,
                                const float* __restrict__ loss,
                                float* __restrict__ out_scalars) {
    __shared__ float red[NE];
    int t = threadIdx.x;   // 512
    float c = counts[t];
    float em = c * (1.f / (float)BATCH);
    red[t] = em * logf(em + 1e-10f);
    __syncthreads();
    for (int s = 256; s; s >>= 1) {
        if (t < s) red[t] += red[t + s];
        __syncthreads();
    }
    if (t == 0) {
        float q = loss[0] * (1.f / ((float)BATCH * (float)ZD));
        out_scalars[0] = q;          // quant_loss
        out_scalars[1] = BETA * q;   // commit_loss
        out_scalars[2] = expf(-red[0]);
    }
}

// ======================================================================
// fc3: out[b,n] = relu(b[n] + sum_k emb[idx[b],k] * w[n,k])   (K=32,N=224)
// ======================================================================
__global__ void fc3_kernel(const float* __restrict__ emb,
                           const int* __restrict__ idx,
                           const float* __restrict__ w,
                           const float* __restrict__ bias,
                           float* __restrict__ out) {
    __shared__ float zq[ZD];
    int b = blockIdx.x, t = threadIdx.x;   // 224
    if (t < ZD) zq[t] = emb[(size_t)idx[b] * ZD + t];
    __syncthreads();
    const float* wp = w + t * ZD;
    float acc = bias[t];
    #pragma unroll
    for (int k = 0; k < ZD; k++) acc += zq[k] * __ldg(wp + k);
    out[(size_t)b * 224 + t] = fmaxf(acc, 0.f);
}

// ======================================================================
// convt1: in[B,32,7,7] -> relu -> out[B,16,14,14]   (k4 s2 p1)
// w[32,16,4,4] (in,out,kh,kw). block = image, 224 threads = (oc=16)x(oy=14)
// ======================================================================
__global__ void convt1_kernel(const float* __restrict__ in,
                              const float* __restrict__ w,
                              const float* __restrict__ bias,
                              float* __restrict__ out) {
    __shared__ float img[1568];
    int b = blockIdx.x, t = threadIdx.x;   // 224
    const float* ip = in + (size_t)b * 1568;
    for (int i = t; i < 1568; i += 224) img[i] = ip[i];
    __syncthreads();
    int oc = t / 14, oy = t % 14;
    float acc[14];
    float bv = bias[oc];
    #pragma unroll
    for (int j = 0; j < 14; j++) acc[j] = bv;
    for (int ic = 0; ic < 32; ic++) {
        const float* xc = img + ic * 49;
        const float* wp = w + ic * 256 + oc * 16;
        #pragma unroll
        for (int ky = 0; ky < 4; ky++) {
            int ty = oy + 1 - ky;
            if (ty < 0 || (ty & 1)) continue;
            int iy = ty >> 1;
            if (iy >= 7) continue;
            float row[7];
            #pragma unroll
            for (int j = 0; j < 7; j++) row[j] = xc[iy * 7 + j];
            #pragma unroll
            for (int kx = 0; kx < 4; kx++) {
                float wv = __ldg(wp + ky * 4 + kx);
                #pragma unroll
                for (int ox = 0; ox < 14; ox++) {
                    int txx = ox + 1 - kx;          // compile-time per (ox,kx)
                    if (txx >= 0 && !(txx & 1) && (txx >> 1) < 7)
                        acc[ox] += row[txx >> 1] * wv;
                }
            }
        }
    }
    float* op = out + (size_t)b * 3136 + oc * 196 + oy * 14;
    #pragma unroll
    for (int ox = 0; ox < 14; ox++) op[ox] = fmaxf(acc[ox], 0.f);
}

// ======================================================================
// convt2: in[B,16,14,14] -> out[B,1,28,28]  (k4 s2 p1, no relu) -> d_out
// ======================================================================
__global__ void convt2_kernel(const float* __restrict__ in,
                              const float* __restrict__ w,
                              const float* __restrict__ bias,
                              float* __restrict__ out) {
    __shared__ float img[3136];
    __shared__ float ws[256];
    int b = blockIdx.x, t = threadIdx.x;   // 256
    const float* ip = in + (size_t)b * 3136;
    for (int i = t; i < 3136; i += 256) img[i] = ip[i];
    if (t < 256) ws[t] = w[t];
    __syncthreads();
    float bv = bias[0];
    float* op = out + (size_t)b * 784;
    for (int o = t; o < 784; o += 256) {
        int oy = o / 28, ox = o % 28;
        float acc = bv;
        #pragma unroll
        for (int ky = 0; ky < 4; ky++) {
            int ty = oy + 1 - ky;
            if (ty < 0 || (ty & 1)) continue;
            int iy = ty >> 1;
            if (iy >= 14) continue;
            #pragma unroll
            for (int kx = 0; kx < 4; kx++) {
                int tx = ox + 1 - kx;
                if (tx < 0 || (tx & 1)) continue;
                int ix = tx >> 1;
                if (ix >= 14) continue;
                #pragma unroll
                for (int ic = 0; ic < 16; ic++)
                    acc += img[ic * 196 + iy * 14 + ix] * ws[ic * 16 + ky * 4 + kx];
            }
        }
        op[o] = acc;
    }
}

// ======================================================================
// launch
// ======================================================================
extern "C" void kernel_launch(void* const* d_in, const int* in_sizes, int n_in,
                              void* d_out, int out_size) {
    const float* x        = (const float*)d_in[0];
    const float* conv1_w  = (const float*)d_in[1];
    const float* conv1_b  = (const float*)d_in[2];
    const float* conv2_w  = (const float*)d_in[3];
    const float* conv2_b  = (const float*)d_in[4];
    const float* res1_w1  = (const float*)d_in[5];
    const float* res1_w2  = (const float*)d_in[6];
    const float* fc1_w    = (const float*)d_in[7];
    const float* fc1_b    = (const float*)d_in[8];
    const float* fc2_w    = (const float*)d_in[9];
    const float* fc2_b    = (const float*)d_in[10];
    const float* emb      = (const float*)d_in[11];
    const float* n_mat    = (const float*)d_in[12];
    const float* m_mat    = (const float*)d_in[13];
    const float* fc3_w    = (const float*)d_in[14];
    const float* fc3_b    = (const float*)d_in[15];
    const float* fc4_w    = (const float*)d_in[16];
    const float* fc4_b    = (const float*)d_in[17];
    const float* res2_w1  = (const float*)d_in[18];
    const float* res2_w2  = (const float*)d_in[19];
    const float* convt1_w = (const float*)d_in[20];
    const float* convt1_b = (const float*)d_in[21];
    const float* convt2_w = (const float*)d_in[22];
    const float* convt2_b = (const float*)d_in[23];
    float* out = (float*)d_out;

    float *h1, *h2, *a, *z, *enorm, *counts, *sums, *loss;
    int* idx;
    cudaGetSymbolAddress((void**)&h1,     g_h1);
    cudaGetSymbolAddress((void**)&h2,     g_h2);
    cudaGetSymbolAddress((void**)&a,      g_a);
    cudaGetSymbolAddress((void**)&z,      g_z);
    cudaGetSymbolAddress((void**)&idx,    g_idx);
    cudaGetSymbolAddress((void**)&enorm,  g_enorm);
    cudaGetSymbolAddress((void**)&counts, g_counts);
    cudaGetSymbolAddress((void**)&sums,   g_sums);
    cudaGetSymbolAddress((void**)&loss,   g_loss);

    // encoder
    conv1_kernel<<<BATCH, 256>>>(x, conv1_w, conv1_b, h1);
    conv2_kernel<<<BATCH, 224>>>(h1, conv2_w, conv2_b, h2);
    res_kernel  <<<BATCH, 448>>>(h2, res1_w1, res1_w2);
    gemm_nt<1><<<dim3(BATCH / 64, (224 + 63) / 64), 256>>>(h2, fc1_w, fc1_b, a,
                                                           BATCH, 224, 1568);
    fc2_kernel<<<BATCH / 8, 256>>>(a, fc2_w, fc2_b, z);

    // VQ
    zero_kernel <<<(NE * ZD + 255) / 256, 256>>>(counts, sums, loss);
    enorm_kernel<<<2, 256>>>(emb, enorm);
    vq_kernel   <<<BATCH / 8, 256>>>(z, emb, enorm, idx, counts, sums, loss);
    embnew_kernel  <<<(NE * ZD + 255) / 256, 256>>>(m_mat, n_mat, sums, counts,
                                                    out + OFF_SCAL + 3);
    finalize_kernel<<<1, NE>>>(counts, loss, out + OFF_SCAL);

    // decoder
    fc3_kernel<<<BATCH, 224>>>(emb, idx, fc3_w, fc3_b, a);
    gemm_nt<1><<<dim3(BATCH / 64, (1568 + 63) / 64), 256>>>(a, fc4_w, fc4_b, h2,
                                                            BATCH, 1568, 224);
    res_kernel   <<<BATCH, 448>>>(h2, res2_w1, res2_w2);
    convt1_kernel<<<BATCH, 224>>>(h2, convt1_w, convt1_b, h1);
    convt2_kernel<<<BATCH, 256>>>(h1, convt2_w, convt2_b, out);
}